// round 13
// baseline (speedup 1.0000x reference)
#include <cuda_runtime.h>
#include <cstdint>

// Problem shape (fixed by the dataset)
#define B_ROWS    16384
#define D_DIM     2048
#define D4        512                 // float4 per row (8 KB)
#define ROW_BYTES 8192
#define NBLK      592                 // 148 SMs x 4 CTAs, persistent, one wave
#define NTHR      256
#define STAGES    6                   // 6 x 8 KB ring = 48 KB/CTA (192 KB/SM)
#define WARPS_PER_BLK (NTHR / 32)

__device__ float g_partials[NBLK];
__device__ unsigned int g_count;      // zero-init at load; reset by last block

__device__ __forceinline__ uint32_t smem_u32(const void* p) {
    return (uint32_t)__cvta_generic_to_shared(p);
}
__device__ __forceinline__ void mbar_init(uint32_t mbar, uint32_t cnt) {
    asm volatile("mbarrier.init.shared.b64 [%0], %1;" :: "r"(mbar), "r"(cnt) : "memory");
}
__device__ __forceinline__ void mbar_expect_tx(uint32_t mbar, uint32_t bytes) {
    asm volatile("mbarrier.arrive.expect_tx.shared.b64 _, [%0], %1;"
                 :: "r"(mbar), "r"(bytes) : "memory");
}
__device__ __forceinline__ void mbar_arrive(uint32_t mbar) {
    asm volatile("mbarrier.arrive.release.cta.shared::cta.b64 _, [%0];"
                 :: "r"(mbar) : "memory");
}
__device__ __forceinline__ void bulk_g2s(uint32_t dst, const void* src,
                                         uint32_t bytes, uint32_t mbar) {
    asm volatile(
        "cp.async.bulk.shared::cluster.global.mbarrier::complete_tx::bytes "
        "[%0], [%1], %2, [%3];"
        :: "r"(dst), "l"(src), "r"(bytes), "r"(mbar) : "memory");
}
__device__ __forceinline__ void mbar_wait(uint32_t mbar, uint32_t parity) {
    asm volatile(
        "{\n\t"
        ".reg .pred P;\n\t"
        "W%=:\n\t"
        "mbarrier.try_wait.parity.acquire.cta.shared::cta.b64 P, [%0], %1, 0x989680;\n\t"
        "@!P bra W%=;\n\t"
        "}"
        :: "r"(mbar), "r"(parity) : "memory");
}

// R11 topology (592x256, 4 CTA/SM, 8KB bulk-copy stages) with the cadence
// taxes removed: consumer __syncthreads replaced by empty-mbarrier arrives
// (non-blocking), ring deepened to 6, sleep-hint waits, s register-resident.
__global__ __launch_bounds__(NTHR, 4) void fused_loss_kernel(
    const float* __restrict__ x,
    const int* __restrict__ pol,      // int32 (JAX x64-disabled downcasts int64)
    const float* __restrict__ s,
    float* __restrict__ out)
{
    extern __shared__ float4 ring[];                 // STAGES * D4 float4 = 48 KB
    __shared__ alignas(8) unsigned long long full_mb[STAGES];
    __shared__ alignas(8) unsigned long long empty_mb[STAGES];

    const float4* __restrict__ s4 = (const float4*)s;
    const int tid = threadIdx.x;
    const int bid = blockIdx.x;

    // contiguous row range for this CTA (27 or 28 rows)
    const int r0 = (int)(((long long)bid * B_ROWS) / NBLK);
    const int r1 = (int)(((long long)(bid + 1) * B_ROWS) / NBLK);
    const int nrows = r1 - r0;

    const uint32_t ring_base  = smem_u32(ring);
    const uint32_t full_base  = smem_u32(&full_mb[0]);
    const uint32_t empty_base = smem_u32(&empty_mb[0]);

    if (tid == 0) {
#pragma unroll
        for (int st = 0; st < STAGES; st++) {
            mbar_init(full_base  + 8 * st, 1);       // tx-completion
            mbar_init(empty_base + 8 * st, NTHR);    // all consumers arrive
        }
        asm volatile("fence.proxy.async.shared::cta;" ::: "memory");
    }
    __syncthreads();

    // register-resident score table: 3 candidates for each of 2 owned columns
    const float4 sA0 = __ldg(&s4[tid]);
    const float4 sA1 = __ldg(&s4[D4 + tid]);
    const float4 sA2 = __ldg(&s4[2 * D4 + tid]);
    const float4 sB0 = __ldg(&s4[tid + NTHR]);
    const float4 sB1 = __ldg(&s4[D4 + tid + NTHR]);
    const float4 sB2 = __ldg(&s4[2 * D4 + tid + NTHR]);

    // prologue: fill the ring (buffers initially free)
    if (tid == 0) {
#pragma unroll
        for (int k = 0; k < STAGES; k++) {
            if (k < nrows) {
                uint32_t mb = full_base + 8 * k;
                mbar_expect_tx(mb, ROW_BYTES);
                bulk_g2s(ring_base + k * ROW_BYTES,
                         x + (size_t)(r0 + k) * D_DIM, ROW_BYTES, mb);
            }
        }
    }

    float a0 = 0.f, a1 = 0.f, a2 = 0.f, a3 = 0.f;

    int st = 0, ph = 0;                              // stage cursor + phase
    for (int k = 0; k < nrows; k++) {
        mbar_wait(full_base + 8 * st, (uint32_t)ph); // data ready (acquire)

        int p = __ldg(&pol[r0 + k]);                 // broadcast load
        p = min(max(p, 0), 2);
        const float4* xr = ring + st * D4;
        float4 xv0 = xr[tid];
        float4 xv1 = xr[tid + NTHR];
        float4 sv0 = (p == 0) ? sA0 : ((p == 1) ? sA1 : sA2);
        float4 sv1 = (p == 0) ? sB0 : ((p == 1) ? sB1 : sB2);

        float d0 = xv0.x - sv0.x, d1 = xv0.y - sv0.y;
        float d2 = xv0.z - sv0.z, d3 = xv0.w - sv0.w;
        a0 += d0 * d0;  a1 += d1 * d1;
        a2 += d2 * d2;  a3 += d3 * d3;
        d0 = xv1.x - sv1.x; d1 = xv1.y - sv1.y;
        d2 = xv1.z - sv1.z; d3 = xv1.w - sv1.w;
        a0 += d0 * d0;  a1 += d1 * d1;
        a2 += d2 * d2;  a3 += d3 * d3;

        mbar_arrive(empty_base + 8 * st);            // slot consumed (non-blocking)

        if (tid == 0 && k + STAGES < nrows) {
            // wait for all 256 consumers of THIS slot's current occupancy
            mbar_wait(empty_base + 8 * st, (uint32_t)ph);
            uint32_t mb = full_base + 8 * st;
            mbar_expect_tx(mb, ROW_BYTES);
            bulk_g2s(ring_base + st * ROW_BYTES,
                     x + (size_t)(r0 + k + STAGES) * D_DIM, ROW_BYTES, mb);
        }
        if (++st == STAGES) { st = 0; ph ^= 1; }
    }
    float acc = (a0 + a1) + (a2 + a3);

    // ---- block reduce ----
    const int wid  = tid >> 5;
    const int lane = tid & 31;
#pragma unroll
    for (int off = 16; off > 0; off >>= 1)
        acc += __shfl_down_sync(0xFFFFFFFFu, acc, off);

    __shared__ float wsum[WARPS_PER_BLK];
    if (lane == 0) wsum[wid] = acc;
    __syncthreads();

    __shared__ unsigned int s_islast;
    if (tid == 0) {
        float bsum = 0.f;
#pragma unroll
        for (int w = 0; w < WARPS_PER_BLK; w++) bsum += wsum[w];
        g_partials[bid] = bsum;
        __threadfence();
        unsigned int prev = atomicAdd(&g_count, 1u);
        s_islast = (prev == NBLK - 1) ? 1u : 0u;
    }
    __syncthreads();
    if (!s_islast) return;

    // ---- last block: fold partials + cos^2 terms ----
    float racc = 0.0f;
    for (int j = tid; j < NBLK; j += NTHR) racc += g_partials[j];

    // cos_(a,b) = dot(a,b) / sqrt(||a||^2) * sqrt(||b||^2) (reference precedence)
    // => cos_^2 = dot^2 * ||b||^2 / ||a||^2
    float n0 = 0.f, n1 = 0.f, n2 = 0.f, d01 = 0.f, d02 = 0.f, d12 = 0.f;
    for (int j = tid; j < D_DIM; j += NTHR) {
        float a = s[j];
        float b = s[D_DIM + j];
        float c = s[2 * D_DIM + j];
        n0  += a * a;  n1  += b * b;  n2  += c * c;
        d01 += a * b;  d02 += a * c;  d12 += b * c;
    }

    __shared__ float rm[7][NTHR];
    rm[0][tid] = racc;
    rm[1][tid] = n0;  rm[2][tid] = n1;  rm[3][tid] = n2;
    rm[4][tid] = d01; rm[5][tid] = d02; rm[6][tid] = d12;
    __syncthreads();
#pragma unroll
    for (int q = NTHR / 2; q > 0; q >>= 1) {
        if (tid < q) {
#pragma unroll
            for (int m = 0; m < 7; m++) rm[m][tid] += rm[m][tid + q];
        }
        __syncthreads();
    }

    if (tid == 0) {
        float L   = rm[0][0];
        float N0  = rm[1][0], N1 = rm[2][0], N2 = rm[3][0];
        float D01 = rm[4][0], D02 = rm[5][0], D12 = rm[6][0];
        float c01 = D01 * D01 * (N1 / N0);
        float c02 = D02 * D02 * (N2 / N0);
        float c12 = D12 * D12 * (N2 / N1);
        out[0] = L + c01 + c02 + c12;
        g_count = 0;                 // reset for next graph replay
    }
}

extern "C" void kernel_launch(void* const* d_in, const int* in_sizes, int n_in,
                              void* d_out, int out_size)
{
    const float* x   = (const float*)d_in[0];   // inputs [16384, 2048] f32
    const int*   pol = (const int*)d_in[1];     // polarity [16384] int32
    const float* s   = (const float*)d_in[2];   // standar_score [3, 2048] f32
    float* out = (float*)d_out;

    static int configured = 0;
    if (!configured) {
        cudaFuncSetAttribute(fused_loss_kernel,
                             cudaFuncAttributeMaxDynamicSharedMemorySize,
                             STAGES * ROW_BYTES);
        configured = 1;
    }
    fused_loss_kernel<<<NBLK, NTHR, STAGES * ROW_BYTES>>>(x, pol, s, out);
}

// round 14
// speedup vs baseline: 1.0689x; 1.0689x over previous
#include <cuda_runtime.h>
#include <cstdint>

// Problem shape (fixed by the dataset)
#define B_ROWS    16384
#define D_DIM     2048
#define D4        512                 // float4 per row (8 KB)
#define ROW_BYTES 8192
#define NBLK      592                 // 148 SMs x 4 CTAs, persistent, one wave
#define NTHR      256
#define CHUNK     2                   // rows per stage (16 KB)
#define STAGES    3                   // 3 x 16 KB = 48 KB/CTA (192 KB/SM in flight)
#define CHUNK_BYTES (CHUNK * ROW_BYTES)
#define WARPS_PER_BLK (NTHR / 32)

__device__ float g_partials[NBLK];
__device__ unsigned int g_count;      // zero-init at load; reset by last block

__device__ __forceinline__ uint32_t smem_u32(const void* p) {
    return (uint32_t)__cvta_generic_to_shared(p);
}
__device__ __forceinline__ void mbar_init(uint32_t mbar, uint32_t cnt) {
    asm volatile("mbarrier.init.shared.b64 [%0], %1;" :: "r"(mbar), "r"(cnt) : "memory");
}
__device__ __forceinline__ void mbar_expect_tx(uint32_t mbar, uint32_t bytes) {
    asm volatile("mbarrier.arrive.expect_tx.shared.b64 _, [%0], %1;"
                 :: "r"(mbar), "r"(bytes) : "memory");
}
__device__ __forceinline__ void bulk_g2s(uint32_t dst, const void* src,
                                         uint32_t bytes, uint32_t mbar) {
    asm volatile(
        "cp.async.bulk.shared::cluster.global.mbarrier::complete_tx::bytes "
        "[%0], [%1], %2, [%3];"
        :: "r"(dst), "l"(src), "r"(bytes), "r"(mbar) : "memory");
}
// try_wait with HW-sleep timeout hint (R11's hint-less spin burned 39% issue)
__device__ __forceinline__ void mbar_wait(uint32_t mbar, uint32_t parity) {
    asm volatile(
        "{\n\t"
        ".reg .pred P;\n\t"
        "W%=:\n\t"
        "mbarrier.try_wait.parity.acquire.cta.shared::cta.b64 P, [%0], %1, 0x989680;\n\t"
        "@!P bra W%=;\n\t"
        "}"
        :: "r"(mbar), "r"(parity) : "memory");
}

// R11 structure (best known: 4.85 TB/s), refined: 16KB (2-row) stages halve
// the per-stage wait+BAR+reissue tax; sleep-hint waits kill the spin burn.
__global__ __launch_bounds__(NTHR, 4) void fused_loss_kernel(
    const float* __restrict__ x,
    const int* __restrict__ pol,      // int32 (JAX x64-disabled downcasts int64)
    const float* __restrict__ s,
    float* __restrict__ out)
{
    extern __shared__ float4 ring[];                 // STAGES*CHUNK*D4 float4 = 48 KB
    __shared__ alignas(8) unsigned long long mbar[STAGES];

    const float4* __restrict__ s4 = (const float4*)s;
    const int tid = threadIdx.x;
    const int bid = blockIdx.x;

    // contiguous row range for this CTA (27 or 28 rows)
    const int r0 = (int)(((long long)bid * B_ROWS) / NBLK);
    const int r1 = (int)(((long long)(bid + 1) * B_ROWS) / NBLK);
    const int nrows  = r1 - r0;
    const int nchunk = (nrows + CHUNK - 1) / CHUNK;  // 14

    const uint32_t ring_base = smem_u32(ring);
    const uint32_t mbar_base = smem_u32(&mbar[0]);

    if (tid == 0) {
#pragma unroll
        for (int st = 0; st < STAGES; st++) mbar_init(mbar_base + 8 * st, 1);
        asm volatile("fence.proxy.async.shared::cta;" ::: "memory");
    }
    __syncthreads();

    // prologue: fill the ring
    if (tid == 0) {
#pragma unroll
        for (int c = 0; c < STAGES; c++) {
            if (c < nchunk) {
                const int rk = r0 + c * CHUNK;
                const uint32_t bytes = (uint32_t)(min(CHUNK, r1 - rk)) * ROW_BYTES;
                uint32_t mb = mbar_base + 8 * c;
                mbar_expect_tx(mb, bytes);
                bulk_g2s(ring_base + c * CHUNK_BYTES,
                         x + (size_t)rk * D_DIM, bytes, mb);
            }
        }
    }

    float a0 = 0.f, a1 = 0.f, a2 = 0.f, a3 = 0.f;

    int st = 0, ph = 0;
    for (int c = 0; c < nchunk; c++) {
        mbar_wait(mbar_base + 8 * st, (uint32_t)ph);

        const int rk = r0 + c * CHUNK;
        const float4* xs = ring + st * (CHUNK * D4);

        // row 0 of chunk (always valid)
        {
            int p = __ldg(&pol[rk]);
            p = min(max(p, 0), 2);
            const float4* sp = s4 + p * D4;
            float4 xv0 = xs[tid];
            float4 xv1 = xs[tid + NTHR];
            float4 sv0 = __ldg(&sp[tid]);
            float4 sv1 = __ldg(&sp[tid + NTHR]);
            float d0 = xv0.x - sv0.x, d1 = xv0.y - sv0.y;
            float d2 = xv0.z - sv0.z, d3 = xv0.w - sv0.w;
            a0 += d0 * d0;  a1 += d1 * d1;
            a2 += d2 * d2;  a3 += d3 * d3;
            d0 = xv1.x - sv1.x; d1 = xv1.y - sv1.y;
            d2 = xv1.z - sv1.z; d3 = xv1.w - sv1.w;
            a0 += d0 * d0;  a1 += d1 * d1;
            a2 += d2 * d2;  a3 += d3 * d3;
        }
        // row 1 of chunk (guard the tail)
        if (rk + 1 < r1) {
            int p = __ldg(&pol[rk + 1]);
            p = min(max(p, 0), 2);
            const float4* sp = s4 + p * D4;
            float4 xv0 = xs[D4 + tid];
            float4 xv1 = xs[D4 + tid + NTHR];
            float4 sv0 = __ldg(&sp[tid]);
            float4 sv1 = __ldg(&sp[tid + NTHR]);
            float d0 = xv0.x - sv0.x, d1 = xv0.y - sv0.y;
            float d2 = xv0.z - sv0.z, d3 = xv0.w - sv0.w;
            a0 += d0 * d0;  a1 += d1 * d1;
            a2 += d2 * d2;  a3 += d3 * d3;
            d0 = xv1.x - sv1.x; d1 = xv1.y - sv1.y;
            d2 = xv1.z - sv1.z; d3 = xv1.w - sv1.w;
            a0 += d0 * d0;  a1 += d1 * d1;
            a2 += d2 * d2;  a3 += d3 * d3;
        }
        __syncthreads();                             // stage st fully consumed

        const int cn = c + STAGES;
        if (tid == 0 && cn < nchunk) {
            const int rn = r0 + cn * CHUNK;
            const uint32_t bytes = (uint32_t)(min(CHUNK, r1 - rn)) * ROW_BYTES;
            uint32_t mb = mbar_base + 8 * st;
            mbar_expect_tx(mb, bytes);
            bulk_g2s(ring_base + st * CHUNK_BYTES,
                     x + (size_t)rn * D_DIM, bytes, mb);
        }
        if (++st == STAGES) { st = 0; ph ^= 1; }
    }
    float acc = (a0 + a1) + (a2 + a3);

    // ---- block reduce ----
    const int wid  = tid >> 5;
    const int lane = tid & 31;
#pragma unroll
    for (int off = 16; off > 0; off >>= 1)
        acc += __shfl_down_sync(0xFFFFFFFFu, acc, off);

    __shared__ float wsum[WARPS_PER_BLK];
    if (lane == 0) wsum[wid] = acc;
    __syncthreads();

    __shared__ unsigned int s_islast;
    if (tid == 0) {
        float bsum = 0.f;
#pragma unroll
        for (int w = 0; w < WARPS_PER_BLK; w++) bsum += wsum[w];
        g_partials[bid] = bsum;
        __threadfence();
        unsigned int prev = atomicAdd(&g_count, 1u);
        s_islast = (prev == NBLK - 1) ? 1u : 0u;
    }
    __syncthreads();
    if (!s_islast) return;

    // ---- last block: fold partials + cos^2 terms ----
    float racc = 0.0f;
    for (int j = tid; j < NBLK; j += NTHR) racc += g_partials[j];

    // cos_(a,b) = dot(a,b) / sqrt(||a||^2) * sqrt(||b||^2) (reference precedence)
    // => cos_^2 = dot^2 * ||b||^2 / ||a||^2
    float n0 = 0.f, n1 = 0.f, n2 = 0.f, d01 = 0.f, d02 = 0.f, d12 = 0.f;
    for (int j = tid; j < D_DIM; j += NTHR) {
        float a = s[j];
        float b = s[D_DIM + j];
        float c = s[2 * D_DIM + j];
        n0  += a * a;  n1  += b * b;  n2  += c * c;
        d01 += a * b;  d02 += a * c;  d12 += b * c;
    }

    __shared__ float rm[7][NTHR];
    rm[0][tid] = racc;
    rm[1][tid] = n0;  rm[2][tid] = n1;  rm[3][tid] = n2;
    rm[4][tid] = d01; rm[5][tid] = d02; rm[6][tid] = d12;
    __syncthreads();
#pragma unroll
    for (int q = NTHR / 2; q > 0; q >>= 1) {
        if (tid < q) {
#pragma unroll
            for (int m = 0; m < 7; m++) rm[m][tid] += rm[m][tid + q];
        }
        __syncthreads();
    }

    if (tid == 0) {
        float L   = rm[0][0];
        float N0  = rm[1][0], N1 = rm[2][0], N2 = rm[3][0];
        float D01 = rm[4][0], D02 = rm[5][0], D12 = rm[6][0];
        float c01 = D01 * D01 * (N1 / N0);
        float c02 = D02 * D02 * (N2 / N0);
        float c12 = D12 * D12 * (N2 / N1);
        out[0] = L + c01 + c02 + c12;
        g_count = 0;                 // reset for next graph replay
    }
}

extern "C" void kernel_launch(void* const* d_in, const int* in_sizes, int n_in,
                              void* d_out, int out_size)
{
    const float* x   = (const float*)d_in[0];   // inputs [16384, 2048] f32
    const int*   pol = (const int*)d_in[1];     // polarity [16384] int32
    const float* s   = (const float*)d_in[2];   // standar_score [3, 2048] f32
    float* out = (float*)d_out;

    static int configured = 0;
    if (!configured) {
        cudaFuncSetAttribute(fused_loss_kernel,
                             cudaFuncAttributeMaxDynamicSharedMemorySize,
                             STAGES * CHUNK_BYTES);
        configured = 1;
    }
    fused_loss_kernel<<<NBLK, NTHR, STAGES * CHUNK_BYTES>>>(x, pol, s, out);
}